// round 1
// baseline (speedup 1.0000x reference)
#include <cuda_runtime.h>

// Problem constants
#define SEQ   4096
#define DEMB  512
#define NH    8
#define DH    64
#define QKVN  1536   // 3*DEMB

// Scratch (device globals; no allocation allowed)
__device__ float g_qkv[SEQ * QKVN];    // [S, 3D] : q | k | v
__device__ float g_attn[SEQ * DEMB];   // [S, D] merged-head attention output

// ---------------------------------------------------------------------------
// Tiled SGEMM with bias: C[M,N] = A[M,K] @ B[K,N] + bias[N]
// BM=BN=128, BK=8, 256 threads, 8x8 register micro-tile.
// Requires M%128==0, N%128==0, K%8==0 (true for all three GEMMs here).
// ---------------------------------------------------------------------------
__global__ __launch_bounds__(256)
void gemm_bias(const float* __restrict__ A, const float* __restrict__ B,
               const float* __restrict__ bias, float* __restrict__ C,
               int M, int N, int K) {
    constexpr int BM = 128, BN = 128, BK = 8, TM = 8, TN = 8;
    __shared__ float As[BK][BM];   // A tile stored transposed
    __shared__ float Bs[BK][BN];

    const int tid = threadIdx.x;
    const int bm  = blockIdx.y * BM;
    const int bn  = blockIdx.x * BN;

    // loader indices
    const int a_row = tid >> 1;          // 0..127
    const int a_col = (tid & 1) * 4;     // 0 or 4
    const int b_row = tid >> 5;          // 0..7
    const int b_col = (tid & 31) * 4;    // 0..124

    // compute indices
    const int ty = tid >> 4;             // 0..15
    const int tx = tid & 15;             // 0..15

    float acc[TM][TN] = {};

    for (int k0 = 0; k0 < K; k0 += BK) {
        float4 av = *(const float4*)&A[(size_t)(bm + a_row) * K + k0 + a_col];
        As[a_col + 0][a_row] = av.x;
        As[a_col + 1][a_row] = av.y;
        As[a_col + 2][a_row] = av.z;
        As[a_col + 3][a_row] = av.w;
        *(float4*)&Bs[b_row][b_col] =
            *(const float4*)&B[(size_t)(k0 + b_row) * N + bn + b_col];
        __syncthreads();

        #pragma unroll
        for (int k = 0; k < BK; k++) {
            float ra[TM], rb[TN];
            #pragma unroll
            for (int i = 0; i < TM; i++) ra[i] = As[k][ty * TM + i];
            #pragma unroll
            for (int j = 0; j < TN; j++) rb[j] = Bs[k][tx * TN + j];
            #pragma unroll
            for (int i = 0; i < TM; i++)
                #pragma unroll
                for (int j = 0; j < TN; j++)
                    acc[i][j] += ra[i] * rb[j];
        }
        __syncthreads();
    }

    #pragma unroll
    for (int i = 0; i < TM; i++) {
        const size_t row = bm + ty * TM + i;
        #pragma unroll
        for (int j = 0; j < TN; j += 4) {
            const int col = bn + tx * TN + j;
            float4 v;
            v.x = acc[i][j + 0] + bias[col + 0];
            v.y = acc[i][j + 1] + bias[col + 1];
            v.z = acc[i][j + 2] + bias[col + 2];
            v.w = acc[i][j + 3] + bias[col + 3];
            *(float4*)&C[row * N + col] = v;
        }
    }
}

// ---------------------------------------------------------------------------
// Causal flash attention, fp32.
// Grid: (S/64, NH). 64 threads per block; thread t owns query row qt*64+t.
// q[64] and o[64] live in registers. K^T, V^T, S tiles in smem:
//   Ks[k][j] / Vs[k][j]  -> reads are warp-broadcast (same addr all lanes)
//   Ss[j][tid]           -> bank = tid%32, conflict-free
// Smem = 3 * 64*64*4 = 48 KB exactly (static limit).
// ---------------------------------------------------------------------------
__global__ __launch_bounds__(64)
void attn_kernel(const float* __restrict__ qkv, float* __restrict__ attn) {
    __shared__ float Ks[DH][64];   // K^T tile: [k][j]
    __shared__ float Vs[DH][64];   // V^T tile: [k][j]
    __shared__ float Ss[64][64];   // scores:   [j][row]

    const int tid = threadIdx.x;       // query row within tile
    const int qt  = blockIdx.x;        // query tile
    const int h   = blockIdx.y;        // head
    const int qrow = qt * 64 + tid;

    // load q row into registers (float4)
    float q[DH];
    const float* qptr = &qkv[(size_t)qrow * QKVN + h * DH];
    #pragma unroll
    for (int k = 0; k < DH; k += 4) {
        float4 v = *(const float4*)&qptr[k];
        q[k] = v.x; q[k + 1] = v.y; q[k + 2] = v.z; q[k + 3] = v.w;
    }

    float o[DH] = {};
    float m = -INFINITY, l = 0.f;

    for (int kt = 0; kt <= qt; kt++) {
        // cooperative load: thread tid loads K/V row (kt*64+tid), stores transposed
        {
            const size_t base = (size_t)(kt * 64 + tid) * QKVN + h * DH;
            const float* kp = &qkv[base + DEMB];       // k starts at +512
            const float* vp = &qkv[base + 2 * DEMB];   // v starts at +1024
            #pragma unroll
            for (int k = 0; k < DH; k += 4) {
                float4 kv = *(const float4*)&kp[k];
                float4 vv = *(const float4*)&vp[k];
                Ks[k + 0][tid] = kv.x; Ks[k + 1][tid] = kv.y;
                Ks[k + 2][tid] = kv.z; Ks[k + 3][tid] = kv.w;
                Vs[k + 0][tid] = vv.x; Vs[k + 1][tid] = vv.y;
                Vs[k + 2][tid] = vv.z; Vs[k + 3][tid] = vv.w;
            }
        }
        __syncthreads();

        const bool diag = (kt == qt);
        float mloc = m;
        #pragma unroll 2
        for (int j = 0; j < 64; j++) {
            float s = 0.f;
            #pragma unroll
            for (int k = 0; k < DH; k++) s += q[k] * Ks[k][j];
            s *= 0.125f;                       // 1/sqrt(64)
            if (diag && j > tid) s = -INFINITY;
            Ss[j][tid] = s;
            mloc = fmaxf(mloc, s);
        }

        const float corr = __expf(m - mloc);   // 0 on first tile (m = -inf)
        m = mloc;
        l *= corr;
        #pragma unroll
        for (int k = 0; k < DH; k++) o[k] *= corr;

        #pragma unroll 2
        for (int j = 0; j < 64; j++) {
            const float p = __expf(Ss[j][tid] - m);
            l += p;
            #pragma unroll
            for (int k = 0; k < DH; k++) o[k] += p * Vs[k][j];
        }
        __syncthreads();   // protect Ks/Vs before next tile's load
    }

    const float inv = 1.f / l;
    float* op = &attn[(size_t)qrow * DEMB + h * DH];
    #pragma unroll
    for (int k = 0; k < DH; k += 4) {
        float4 v;
        v.x = o[k + 0] * inv; v.y = o[k + 1] * inv;
        v.z = o[k + 2] * inv; v.w = o[k + 3] * inv;
        *(float4*)&op[k] = v;
    }
}

// ---------------------------------------------------------------------------
// Launch
// Inputs (metadata order): x [1,4096,512] f32, W_in [512,1536] f32,
// b_in [1536] f32, W_out [512,512] f32, b_out [512] f32, causal_mask (=1)
// Output: [1,4096,512] f32
// ---------------------------------------------------------------------------
extern "C" void kernel_launch(void* const* d_in, const int* in_sizes, int n_in,
                              void* d_out, int out_size) {
    const float* x     = (const float*)d_in[0];
    const float* W_in  = (const float*)d_in[1];
    const float* b_in  = (const float*)d_in[2];
    const float* W_out = (const float*)d_in[3];
    const float* b_out = (const float*)d_in[4];
    float* out = (float*)d_out;

    float* qkv  = nullptr;
    float* attn = nullptr;
    cudaGetSymbolAddress((void**)&qkv,  g_qkv);
    cudaGetSymbolAddress((void**)&attn, g_attn);

    // 1. QKV projection: [4096,512] @ [512,1536] + b_in
    gemm_bias<<<dim3(QKVN / 128, SEQ / 128), 256>>>(x, W_in, b_in, qkv,
                                                    SEQ, QKVN, DEMB);
    // 2. Causal flash attention per head
    attn_kernel<<<dim3(SEQ / 64, NH), 64>>>(qkv, attn);

    // 3. Output projection: [4096,512] @ [512,512] + b_out
    gemm_bias<<<dim3(DEMB / 128, SEQ / 128), 256>>>(attn, W_out, b_out, out,
                                                    SEQ, DEMB, DEMB);
}

// round 6
// speedup vs baseline: 1.9343x; 1.9343x over previous
#include <cuda_runtime.h>

// Problem constants
#define SEQ   4096
#define DEMB  512
#define NH    8
#define DH    64
#define QKVN  1536   // 3*DEMB

// Scratch (device globals; no allocation allowed)
__device__ float g_qkv[SEQ * QKVN];    // [S, 3D] : q | k | v
__device__ float g_attn[SEQ * DEMB];   // [S, D] merged-head attention output

// ---------------------------------------------------------------------------
// Tiled SGEMM with bias: C[M,N] = A[M,K] @ B[K,N] + bias[N]
// ---------------------------------------------------------------------------
__global__ __launch_bounds__(256)
void gemm_bias(const float* __restrict__ A, const float* __restrict__ B,
               const float* __restrict__ bias, float* __restrict__ C,
               int M, int N, int K) {
    constexpr int BM = 128, BN = 128, BK = 8, TM = 8, TN = 8;
    __shared__ float As[BK][BM];
    __shared__ float Bs[BK][BN];

    const int tid = threadIdx.x;
    const int bm  = blockIdx.y * BM;
    const int bn  = blockIdx.x * BN;

    const int a_row = tid >> 1;
    const int a_col = (tid & 1) * 4;
    const int b_row = tid >> 5;
    const int b_col = (tid & 31) * 4;

    const int ty = tid >> 4;
    const int tx = tid & 15;

    float acc[TM][TN] = {};

    for (int k0 = 0; k0 < K; k0 += BK) {
        float4 av = *(const float4*)&A[(size_t)(bm + a_row) * K + k0 + a_col];
        As[a_col + 0][a_row] = av.x;
        As[a_col + 1][a_row] = av.y;
        As[a_col + 2][a_row] = av.z;
        As[a_col + 3][a_row] = av.w;
        *(float4*)&Bs[b_row][b_col] =
            *(const float4*)&B[(size_t)(k0 + b_row) * N + bn + b_col];
        __syncthreads();

        #pragma unroll
        for (int k = 0; k < BK; k++) {
            float ra[TM], rb[TN];
            #pragma unroll
            for (int i = 0; i < TM; i++) ra[i] = As[k][ty * TM + i];
            #pragma unroll
            for (int j = 0; j < TN; j++) rb[j] = Bs[k][tx * TN + j];
            #pragma unroll
            for (int i = 0; i < TM; i++)
                #pragma unroll
                for (int j = 0; j < TN; j++)
                    acc[i][j] += ra[i] * rb[j];
        }
        __syncthreads();
    }

    #pragma unroll
    for (int i = 0; i < TM; i++) {
        const size_t row = bm + ty * TM + i;
        #pragma unroll
        for (int j = 0; j < TN; j += 4) {
            const int col = bn + tx * TN + j;
            float4 v;
            v.x = acc[i][j + 0] + bias[col + 0];
            v.y = acc[i][j + 1] + bias[col + 1];
            v.z = acc[i][j + 2] + bias[col + 2];
            v.w = acc[i][j + 3] + bias[col + 3];
            *(float4*)&C[row * N + col] = v;
        }
    }
}

// ---------------------------------------------------------------------------
// Causal flash attention, fp32, GEMM-style register tiling.
// Grid: (S/64, NH). 256 threads; thread (ty,tx) owns a 4x4 micro-tile of the
// 64x64 score tile (rows i = ty*4.., cols j = tx*4..) and a 4x4 micro-tile of
// the 64x64 output tile (rows i, cols d = tx*4..).
//
// Smem (exactly 48 KB):
//   Qs[k][i]   : Q tile, k-major (transposed at load)
//   KP[64][64] : K tile k-major for GEMM1; overlaid with P tile (j-major,
//                XOR-swizzled: element (j,i) at col4 = (i>>2)^(j>>2))
//   Vs[64][64] : V tile j-major, XOR-swizzled: (j,d) at col4 = (d>>2)^(j&15)
// All GEMM inner-loop LDS.128 are conflict-free per quarter-warp phase.
// Row softmax stats (m,l) replicated across the 16 tx lanes via shfl.xor.
// ---------------------------------------------------------------------------
__global__ __launch_bounds__(256)
void attn_kernel(const float* __restrict__ qkv, float* __restrict__ attn) {
    __shared__ float Qs[DH][64];
    __shared__ float KP[64][64];
    __shared__ float Vs[64][64];

    const int tid = threadIdx.x;
    const int ty  = tid >> 4;       // 0..15
    const int tx  = tid & 15;       // 0..15
    const int h   = blockIdx.y;
    const int qt  = gridDim.x - 1 - blockIdx.x;   // heavy blocks first

    // ---- load Q tile transposed into Qs[k][i] ----
    {
        const int i  = tid >> 2;        // 0..63 query row in tile
        const int q4 = tid & 3;         // 16-float segment
        const float* qp = &qkv[(size_t)(qt * 64 + i) * QKVN + h * DH + q4 * 16];
        #pragma unroll
        for (int c = 0; c < 4; c++) {
            float4 v = *(const float4*)(qp + c * 4);
            const int k0 = q4 * 16 + c * 4;
            Qs[k0 + 0][i] = v.x; Qs[k0 + 1][i] = v.y;
            Qs[k0 + 2][i] = v.z; Qs[k0 + 3][i] = v.w;
        }
    }

    float o[4][4] = {};
    float m[4], l[4];
    #pragma unroll
    for (int ii = 0; ii < 4; ii++) { m[ii] = -INFINITY; l[ii] = 0.f; }

    for (int kt = 0; kt <= qt; kt++) {
        // ---- load K (transposed, linear) and V (natural, swizzled) ----
        {
            const int j  = tid >> 2;
            const int q4 = tid & 3;
            const float* kp = &qkv[(size_t)(kt * 64 + j) * QKVN + DEMB + h * DH + q4 * 16];
            const float* vp = kp + DEMB;
            #pragma unroll
            for (int c = 0; c < 4; c++) {
                float4 kv = *(const float4*)(kp + c * 4);
                const int k0 = q4 * 16 + c * 4;
                KP[k0 + 0][j] = kv.x; KP[k0 + 1][j] = kv.y;
                KP[k0 + 2][j] = kv.z; KP[k0 + 3][j] = kv.w;
                float4 vv = *(const float4*)(vp + c * 4);
                const int d4 = q4 * 4 + c;              // col4 index 0..15
                *(float4*)&Vs[j][4 * (d4 ^ (j & 15))] = vv;
            }
        }
        __syncthreads();

        // ---- GEMM1: S = Q @ K^T ----
        float s[4][4] = {};
        #pragma unroll 8
        for (int k = 0; k < DH; k++) {
            const float4 a = *(const float4*)&Qs[k][ty * 4];
            const float4 b = *(const float4*)&KP[k][tx * 4];
            const float ra[4] = {a.x, a.y, a.z, a.w};
            const float rb[4] = {b.x, b.y, b.z, b.w};
            #pragma unroll
            for (int ii = 0; ii < 4; ii++)
                #pragma unroll
                for (int jj = 0; jj < 4; jj++)
                    s[ii][jj] += ra[ii] * rb[jj];
        }
        __syncthreads();   // GEMM1 done before P overwrites KP

        // ---- scale + causal mask ----
        const bool diag = (kt == qt);
        #pragma unroll
        for (int ii = 0; ii < 4; ii++)
            #pragma unroll
            for (int jj = 0; jj < 4; jj++) {
                float v = s[ii][jj] * 0.125f;
                if (diag && (tx * 4 + jj) > (ty * 4 + ii)) v = -INFINITY;
                s[ii][jj] = v;
            }

        // ---- online softmax: row stats over 16 tx lanes ----
        float tmax[4];
        #pragma unroll
        for (int ii = 0; ii < 4; ii++) {
            float t = fmaxf(fmaxf(s[ii][0], s[ii][1]), fmaxf(s[ii][2], s[ii][3]));
            #pragma unroll
            for (int d = 1; d < 16; d <<= 1)
                t = fmaxf(t, __shfl_xor_sync(0xffffffffu, t, d));
            tmax[ii] = t;
        }

        float p[4][4];
        #pragma unroll
        for (int ii = 0; ii < 4; ii++) {
            const float mn   = fmaxf(m[ii], tmax[ii]);
            const float corr = __expf(m[ii] - mn);   // 0 on first tile
            m[ii] = mn;
            float ts = 0.f;
            #pragma unroll
            for (int jj = 0; jj < 4; jj++) {
                const float e = __expf(s[ii][jj] - mn);
                p[ii][jj] = e;
                ts += e;
            }
            #pragma unroll
            for (int d = 1; d < 16; d <<= 1)
                ts += __shfl_xor_sync(0xffffffffu, ts, d);
            l[ii] = l[ii] * corr + ts;
            #pragma unroll
            for (int dd = 0; dd < 4; dd++) o[ii][dd] *= corr;
        }

        // ---- store P^T into KP (swizzled): element (j=4tx+jj, i=4ty..) ----
        #pragma unroll
        for (int jj = 0; jj < 4; jj++) {
            float4 pv = make_float4(p[0][jj], p[1][jj], p[2][jj], p[3][jj]);
            *(float4*)&KP[4 * tx + jj][4 * (ty ^ tx)] = pv;
        }
        __syncthreads();

        // ---- GEMM2: O += P @ V ----
        #pragma unroll 8
        for (int j = 0; j < 64; j++) {
            const float4 a = *(const float4*)&KP[j][4 * (ty ^ (j >> 2))];
            const float4 b = *(const float4*)&Vs[j][4 * (tx ^ (j & 15))];
            const float ra[4] = {a.x, a.y, a.z, a.w};
            const float rb[4] = {b.x, b.y, b.z, b.w};
            #pragma unroll
            for (int ii = 0; ii < 4; ii++)
                #pragma unroll
                for (int dd = 0; dd < 4; dd++)
                    o[ii][dd] += ra[ii] * rb[dd];
        }
        __syncthreads();   // before next tile's K/V overwrite
    }

    // ---- epilogue: normalize and write merged-head output ----
    #pragma unroll
    for (int ii = 0; ii < 4; ii++) {
        const float inv = 1.f / l[ii];
        float4 v;
        v.x = o[ii][0] * inv; v.y = o[ii][1] * inv;
        v.z = o[ii][2] * inv; v.w = o[ii][3] * inv;
        const size_t row = qt * 64 + ty * 4 + ii;
        *(float4*)&attn[row * DEMB + h * DH + tx * 4] = v;
    }
}

// ---------------------------------------------------------------------------
// Launch
// ---------------------------------------------------------------------------
extern "C" void kernel_launch(void* const* d_in, const int* in_sizes, int n_in,
                              void* d_out, int out_size) {
    const float* x     = (const float*)d_in[0];
    const float* W_in  = (const float*)d_in[1];
    const float* b_in  = (const float*)d_in[2];
    const float* W_out = (const float*)d_in[3];
    const float* b_out = (const float*)d_in[4];
    float* out = (float*)d_out;

    float* qkv  = nullptr;
    float* attn = nullptr;
    cudaGetSymbolAddress((void**)&qkv,  g_qkv);
    cudaGetSymbolAddress((void**)&attn, g_attn);

    gemm_bias<<<dim3(QKVN / 128, SEQ / 128), 256>>>(x, W_in, b_in, qkv,
                                                    SEQ, QKVN, DEMB);
    attn_kernel<<<dim3(SEQ / 64, NH), 256>>>(qkv, attn);
    gemm_bias<<<dim3(DEMB / 128, SEQ / 128), 256>>>(attn, W_out, b_out, out,
                                                    SEQ, DEMB, DEMB);
}

// round 7
// speedup vs baseline: 2.6756x; 1.3833x over previous
#include <cuda_runtime.h>
#include <cstdint>

// Problem constants
#define SEQ   4096
#define DEMB  512
#define NH    8
#define DH    64
#define QKVN  1536   // 3*DEMB

// Scratch (device globals; no allocation allowed)
__device__ float g_qkv[SEQ * QKVN];    // [S, 3D] : q | k | v
__device__ float g_attn[SEQ * DEMB];   // [S, D] merged-head attention output

// ---------------------------------------------------------------------------
// Tiled SGEMM with bias: C[M,N] = A[M,K] @ B[K,N] + bias[N]   (unchanged)
// ---------------------------------------------------------------------------
__global__ __launch_bounds__(256)
void gemm_bias(const float* __restrict__ A, const float* __restrict__ B,
               const float* __restrict__ bias, float* __restrict__ C,
               int M, int N, int K) {
    constexpr int BM = 128, BN = 128, BK = 8, TM = 8, TN = 8;
    __shared__ float As[BK][BM];
    __shared__ float Bs[BK][BN];

    const int tid = threadIdx.x;
    const int bm  = blockIdx.y * BM;
    const int bn  = blockIdx.x * BN;

    const int a_row = tid >> 1;
    const int a_col = (tid & 1) * 4;
    const int b_row = tid >> 5;
    const int b_col = (tid & 31) * 4;

    const int ty = tid >> 4;
    const int tx = tid & 15;

    float acc[TM][TN] = {};

    for (int k0 = 0; k0 < K; k0 += BK) {
        float4 av = *(const float4*)&A[(size_t)(bm + a_row) * K + k0 + a_col];
        As[a_col + 0][a_row] = av.x;
        As[a_col + 1][a_row] = av.y;
        As[a_col + 2][a_row] = av.z;
        As[a_col + 3][a_row] = av.w;
        *(float4*)&Bs[b_row][b_col] =
            *(const float4*)&B[(size_t)(k0 + b_row) * N + bn + b_col];
        __syncthreads();

        #pragma unroll
        for (int k = 0; k < BK; k++) {
            float ra[TM], rb[TN];
            #pragma unroll
            for (int i = 0; i < TM; i++) ra[i] = As[k][ty * TM + i];
            #pragma unroll
            for (int j = 0; j < TN; j++) rb[j] = Bs[k][tx * TN + j];
            #pragma unroll
            for (int i = 0; i < TM; i++)
                #pragma unroll
                for (int j = 0; j < TN; j++)
                    acc[i][j] += ra[i] * rb[j];
        }
        __syncthreads();
    }

    #pragma unroll
    for (int i = 0; i < TM; i++) {
        const size_t row = bm + ty * TM + i;
        #pragma unroll
        for (int j = 0; j < TN; j += 4) {
            const int col = bn + tx * TN + j;
            float4 v;
            v.x = acc[i][j + 0] + bias[col + 0];
            v.y = acc[i][j + 1] + bias[col + 1];
            v.z = acc[i][j + 2] + bias[col + 2];
            v.w = acc[i][j + 3] + bias[col + 3];
            *(float4*)&C[row * N + col] = v;
        }
    }
}

// ---------------------------------------------------------------------------
// tf32 helpers
// ---------------------------------------------------------------------------
__device__ __forceinline__ uint32_t f2tf32(float x) {
    uint32_t u;
    asm("cvt.rna.tf32.f32 %0, %1;" : "=r"(u) : "f"(x));
    return u;
}
__device__ __forceinline__ float f2tf32f(float x) {
    return __uint_as_float(f2tf32(x));
}

// mma.sync m16n8k8 tf32: D += A(row) * B(col), fp32 accumulate.
// A frag: a0 (r=g,  c=t), a1 (r=g+8, c=t), a2 (r=g, c=t+4), a3 (r=g+8, c=t+4)
// B frag: b0 (k=t, n=g), b1 (k=t+4, n=g)
// C frag: x (r=g, c=2t), y (r=g, c=2t+1), z (r=g+8, c=2t), w (r=g+8, c=2t+1)
__device__ __forceinline__ void mma_tf32(float4& d, const uint32_t* a,
                                         uint32_t b0, uint32_t b1) {
    asm volatile(
        "mma.sync.aligned.m16n8k8.row.col.f32.tf32.tf32.f32 "
        "{%0,%1,%2,%3}, {%4,%5,%6,%7}, {%8,%9}, {%0,%1,%2,%3};\n"
        : "+f"(d.x), "+f"(d.y), "+f"(d.z), "+f"(d.w)
        : "r"(a[0]), "r"(a[1]), "r"(a[2]), "r"(a[3]), "r"(b0), "r"(b1));
}

// ---------------------------------------------------------------------------
// Causal flash attention, tf32 tensor-core (mma.sync), fp32 softmax/accum.
// Grid (S/64, NH), 128 threads (4 warps). Warp w owns q rows [16w, 16w+16).
// Q kept in registers as 8 A-fragments. Per key tile:
//   KtPs[64][72]: K^T (head-dim major) for GEMM1, then overwritten by P
//   Vsm [64][72]: V row-major (key-major) for GEMM2
// Stride 72 makes every fragment LDS a bank permutation (conflict-free).
// ---------------------------------------------------------------------------
#define ST 72

__global__ __launch_bounds__(128)
void attn_mma(const float* __restrict__ qkv, float* __restrict__ attn) {
    __shared__ float KtPs[64 * ST];
    __shared__ float Vsm[64 * ST];

    const int tid  = threadIdx.x;
    const int lane = tid & 31;
    const int warp = tid >> 5;
    const int g    = lane >> 2;     // group id (row within fragment)
    const int t    = lane & 3;      // thread-in-group
    const int h    = blockIdx.y;
    const int qt   = gridDim.x - 1 - blockIdx.x;   // heavy blocks first

    // ---- stage Q tile (rows [i][k], stride ST, tf32) ----
    {
        const int i  = tid >> 1;
        const int kb = (tid & 1) * 32;
        const float* qp = &qkv[(size_t)(qt * 64 + i) * QKVN + h * DH + kb];
        #pragma unroll
        for (int c = 0; c < 32; c += 4) {
            float4 v = *(const float4*)(qp + c);
            float4 w;
            w.x = f2tf32f(v.x); w.y = f2tf32f(v.y);
            w.z = f2tf32f(v.z); w.w = f2tf32f(v.w);
            *(float4*)&KtPs[i * ST + kb + c] = w;
        }
    }
    __syncthreads();

    // ---- Q fragments (8 k-tiles x 4 regs) ----
    uint32_t qf[8][4];
    #pragma unroll
    for (int k8 = 0; k8 < 8; k8++) {
        const float* qb = &KtPs[(warp * 16 + g) * ST + k8 * 8 + t];
        qf[k8][0] = __float_as_uint(qb[0]);
        qf[k8][1] = __float_as_uint(qb[8 * ST]);
        qf[k8][2] = __float_as_uint(qb[4]);
        qf[k8][3] = __float_as_uint(qb[8 * ST + 4]);
    }
    __syncthreads();   // before K overwrites the staging buffer

    float4 o[8];
    #pragma unroll
    for (int nt = 0; nt < 8; nt++) o[nt] = make_float4(0.f, 0.f, 0.f, 0.f);
    float m0 = -INFINITY, m1 = -INFINITY, l0 = 0.f, l1 = 0.f;

    const int row0 = warp * 16 + g;        // tile-local rows this thread owns
    const int row1 = row0 + 8;

    for (int kt = 0; kt <= qt; kt++) {
        // ---- load K (transposed into KtPs) and V (row-major), tf32 ----
        {
            const int j  = tid >> 1;
            const int kb = (tid & 1) * 32;
            const float* kp = &qkv[(size_t)(kt * 64 + j) * QKVN + DEMB + h * DH + kb];
            const float* vp = kp + DEMB;
            #pragma unroll
            for (int c = 0; c < 32; c += 4) {
                float4 kv = *(const float4*)(kp + c);
                KtPs[(kb + c + 0) * ST + j] = f2tf32f(kv.x);
                KtPs[(kb + c + 1) * ST + j] = f2tf32f(kv.y);
                KtPs[(kb + c + 2) * ST + j] = f2tf32f(kv.z);
                KtPs[(kb + c + 3) * ST + j] = f2tf32f(kv.w);
                float4 vv = *(const float4*)(vp + c);
                float4 w;
                w.x = f2tf32f(vv.x); w.y = f2tf32f(vv.y);
                w.z = f2tf32f(vv.z); w.w = f2tf32f(vv.w);
                *(float4*)&Vsm[j * ST + kb + c] = w;
            }
        }
        __syncthreads();

        // ---- GEMM1: S = Q @ K^T (B frag from KtPs[k][j]) ----
        float4 s[8];
        #pragma unroll
        for (int nt = 0; nt < 8; nt++) s[nt] = make_float4(0.f, 0.f, 0.f, 0.f);
        #pragma unroll
        for (int nt = 0; nt < 8; nt++) {
            #pragma unroll
            for (int k8 = 0; k8 < 8; k8++) {
                const uint32_t b0 = __float_as_uint(KtPs[(k8 * 8 + t) * ST + nt * 8 + g]);
                const uint32_t b1 = __float_as_uint(KtPs[(k8 * 8 + t + 4) * ST + nt * 8 + g]);
                mma_tf32(s[nt], qf[k8], b0, b1);
            }
        }
        __syncthreads();   // KtPs free for P

        // ---- scale + causal mask ----
        const bool diag = (kt == qt);
        #pragma unroll
        for (int nt = 0; nt < 8; nt++) {
            s[nt].x *= 0.125f; s[nt].y *= 0.125f;
            s[nt].z *= 0.125f; s[nt].w *= 0.125f;
            if (diag) {
                const int col = nt * 8 + 2 * t;
                if (col     > row0) s[nt].x = -INFINITY;
                if (col + 1 > row0) s[nt].y = -INFINITY;
                if (col     > row1) s[nt].z = -INFINITY;
                if (col + 1 > row1) s[nt].w = -INFINITY;
            }
        }

        // ---- online softmax (rows row0, row1; quad = lanes sharing g) ----
        float mx0 = -INFINITY, mx1 = -INFINITY;
        #pragma unroll
        for (int nt = 0; nt < 8; nt++) {
            mx0 = fmaxf(mx0, fmaxf(s[nt].x, s[nt].y));
            mx1 = fmaxf(mx1, fmaxf(s[nt].z, s[nt].w));
        }
        mx0 = fmaxf(mx0, __shfl_xor_sync(0xffffffffu, mx0, 1));
        mx0 = fmaxf(mx0, __shfl_xor_sync(0xffffffffu, mx0, 2));
        mx1 = fmaxf(mx1, __shfl_xor_sync(0xffffffffu, mx1, 1));
        mx1 = fmaxf(mx1, __shfl_xor_sync(0xffffffffu, mx1, 2));

        const float mn0 = fmaxf(m0, mx0);
        const float mn1 = fmaxf(m1, mx1);
        const float corr0 = __expf(m0 - mn0);   // 0 on first tile
        const float corr1 = __expf(m1 - mn1);
        m0 = mn0; m1 = mn1;

        float sum0 = 0.f, sum1 = 0.f;
        #pragma unroll
        for (int nt = 0; nt < 8; nt++) {
            s[nt].x = __expf(s[nt].x - mn0);
            s[nt].y = __expf(s[nt].y - mn0);
            s[nt].z = __expf(s[nt].z - mn1);
            s[nt].w = __expf(s[nt].w - mn1);
            sum0 += s[nt].x + s[nt].y;
            sum1 += s[nt].z + s[nt].w;
        }
        sum0 += __shfl_xor_sync(0xffffffffu, sum0, 1);
        sum0 += __shfl_xor_sync(0xffffffffu, sum0, 2);
        sum1 += __shfl_xor_sync(0xffffffffu, sum1, 1);
        sum1 += __shfl_xor_sync(0xffffffffu, sum1, 2);
        l0 = l0 * corr0 + sum0;
        l1 = l1 * corr1 + sum1;
        #pragma unroll
        for (int nt = 0; nt < 8; nt++) {
            o[nt].x *= corr0; o[nt].y *= corr0;
            o[nt].z *= corr1; o[nt].w *= corr1;
        }

        // ---- store P (tf32) into KtPs; C-frag layout -> [row][col] ----
        #pragma unroll
        for (int nt = 0; nt < 8; nt++) {
            float2 p01 = make_float2(f2tf32f(s[nt].x), f2tf32f(s[nt].y));
            float2 p23 = make_float2(f2tf32f(s[nt].z), f2tf32f(s[nt].w));
            *(float2*)&KtPs[row0 * ST + nt * 8 + 2 * t] = p01;
            *(float2*)&KtPs[row1 * ST + nt * 8 + 2 * t] = p23;
        }
        __syncthreads();

        // ---- GEMM2: O += P @ V (A frag from KtPs, B frag from Vsm) ----
        #pragma unroll
        for (int k8 = 0; k8 < 8; k8++) {
            uint32_t a[4];
            const float* pb = &KtPs[row0 * ST + k8 * 8 + t];
            a[0] = __float_as_uint(pb[0]);
            a[1] = __float_as_uint(pb[8 * ST]);
            a[2] = __float_as_uint(pb[4]);
            a[3] = __float_as_uint(pb[8 * ST + 4]);
            #pragma unroll
            for (int nt = 0; nt < 8; nt++) {
                const uint32_t b0 = __float_as_uint(Vsm[(k8 * 8 + t) * ST + nt * 8 + g]);
                const uint32_t b1 = __float_as_uint(Vsm[(k8 * 8 + t + 4) * ST + nt * 8 + g]);
                mma_tf32(o[nt], a, b0, b1);
            }
        }
        __syncthreads();   // before next tile overwrites KtPs/Vsm
    }

    // ---- epilogue: normalize, write merged-head output ----
    const float inv0 = 1.f / l0;
    const float inv1 = 1.f / l1;
    const size_t gr0 = (size_t)(qt * 64 + row0) * DEMB + h * DH;
    const size_t gr1 = (size_t)(qt * 64 + row1) * DEMB + h * DH;
    #pragma unroll
    for (int nt = 0; nt < 8; nt++) {
        const int col = nt * 8 + 2 * t;
        *(float2*)&attn[gr0 + col] = make_float2(o[nt].x * inv0, o[nt].y * inv0);
        *(float2*)&attn[gr1 + col] = make_float2(o[nt].z * inv1, o[nt].w * inv1);
    }
}

// ---------------------------------------------------------------------------
// Launch
// ---------------------------------------------------------------------------
extern "C" void kernel_launch(void* const* d_in, const int* in_sizes, int n_in,
                              void* d_out, int out_size) {
    const float* x     = (const float*)d_in[0];
    const float* W_in  = (const float*)d_in[1];
    const float* b_in  = (const float*)d_in[2];
    const float* W_out = (const float*)d_in[3];
    const float* b_out = (const float*)d_in[4];
    float* out = (float*)d_out;

    float* qkv  = nullptr;
    float* attn = nullptr;
    cudaGetSymbolAddress((void**)&qkv,  g_qkv);
    cudaGetSymbolAddress((void**)&attn, g_attn);

    gemm_bias<<<dim3(QKVN / 128, SEQ / 128), 256>>>(x, W_in, b_in, qkv,
                                                    SEQ, QKVN, DEMB);
    attn_mma<<<dim3(SEQ / 64, NH), 128>>>(qkv, attn);
    gemm_bias<<<dim3(DEMB / 128, SEQ / 128), 256>>>(attn, W_out, b_out, out,
                                                    SEQ, DEMB, DEMB);
}

// round 10
// speedup vs baseline: 3.5123x; 1.3127x over previous
#include <cuda_runtime.h>
#include <cstdint>

// Problem constants
#define SEQ   4096
#define DEMB  512
#define NH    8
#define DH    64
#define QKVN  1536   // 3*DEMB

// Scratch (device globals; no allocation allowed)
__device__ float g_qkv[SEQ * QKVN];    // [S, 3D] : q | k | v
__device__ float g_attn[SEQ * DEMB];   // [S, D] merged-head attention output

// ---------------------------------------------------------------------------
// tf32 helpers
// ---------------------------------------------------------------------------
__device__ __forceinline__ uint32_t f2tf32(float x) {
    uint32_t u;
    asm("cvt.rna.tf32.f32 %0, %1;" : "=r"(u) : "f"(x));
    return u;
}
__device__ __forceinline__ float f2tf32f(float x) {
    return __uint_as_float(f2tf32(x));
}

// mma.sync m16n8k8 tf32: D += A(row) * B(col), fp32 accumulate.
// A frag: a0 (r=g,  c=t), a1 (r=g+8, c=t), a2 (r=g, c=t+4), a3 (r=g+8, c=t+4)
// B frag: b0 (k=t, n=g), b1 (k=t+4, n=g)
// C frag: x (r=g, c=2t), y (r=g, c=2t+1), z (r=g+8, c=2t), w (r=g+8, c=2t+1)
__device__ __forceinline__ void mma_tf32(float4& d, const uint32_t* a,
                                         uint32_t b0, uint32_t b1) {
    asm volatile(
        "mma.sync.aligned.m16n8k8.row.col.f32.tf32.tf32.f32 "
        "{%0,%1,%2,%3}, {%4,%5,%6,%7}, {%8,%9}, {%0,%1,%2,%3};\n"
        : "+f"(d.x), "+f"(d.y), "+f"(d.z), "+f"(d.w)
        : "r"(a[0]), "r"(a[1]), "r"(a[2]), "r"(a[3]), "r"(b0), "r"(b1));
}

// ---------------------------------------------------------------------------
// tf32 tensor-core GEMM with bias: C[M,N] = A[M,K] @ B[K,N] + bias[N]
// BM=BN=128, BK=32, 256 threads = 8 warps (4x2); warp tile 32x64
// (2 m-frags x 8 n-frags of m16n8k8). fp32 accumulate.
//   As[128][36] row-major  : A-frag LDS bank = 4g+t   (perm, conflict-free)
//   Bs[32][136] k-major    : B-frag LDS bank = 8t+g+c (perm, conflict-free)
// Requires M%128==0, N%128==0, K%32==0.
// ---------------------------------------------------------------------------
#define AST 36
#define BST 136

__global__ __launch_bounds__(256)
void gemm_bias(const float* __restrict__ A, const float* __restrict__ B,
               const float* __restrict__ bias, float* __restrict__ C,
               int M, int N, int K) {
    __shared__ float As[128 * AST];
    __shared__ float Bs[32 * BST];

    const int tid  = threadIdx.x;
    const int lane = tid & 31;
    const int warp = tid >> 5;
    const int g    = lane >> 2;
    const int t    = lane & 3;
    const int wm   = warp >> 1;          // 0..3
    const int wn   = warp & 1;           // 0..1
    const int bm   = blockIdx.y * 128;
    const int bn   = blockIdx.x * 128;

    // loader indices (gmem-coalesced, smem-conflict-free)
    const int la_row = tid >> 3;         // 0..31 (A: 8 threads/row)
    const int la_c   = (tid & 7) * 4;    // float4 within 32-float row
    const int lb_k   = tid >> 5;         // 0..7  (B: 32 threads/row)
    const int lb_n   = (tid & 31) * 4;

    float4 acc[2][8];
    #pragma unroll
    for (int i = 0; i < 2; i++)
        #pragma unroll
        for (int j = 0; j < 8; j++) acc[i][j] = make_float4(0.f, 0.f, 0.f, 0.f);

    for (int k0 = 0; k0 < K; k0 += 32) {
        // ---- stage A (128x32) and B (32x128), converted to tf32 ----
        #pragma unroll
        for (int p = 0; p < 4; p++) {
            const int row = p * 32 + la_row;
            float4 v = *(const float4*)&A[(size_t)(bm + row) * K + k0 + la_c];
            v.x = f2tf32f(v.x); v.y = f2tf32f(v.y);
            v.z = f2tf32f(v.z); v.w = f2tf32f(v.w);
            *(float4*)&As[row * AST + la_c] = v;
        }
        #pragma unroll
        for (int p = 0; p < 4; p++) {
            const int k = p * 8 + lb_k;
            float4 v = *(const float4*)&B[(size_t)(k0 + k) * N + bn + lb_n];
            v.x = f2tf32f(v.x); v.y = f2tf32f(v.y);
            v.z = f2tf32f(v.z); v.w = f2tf32f(v.w);
            *(float4*)&Bs[k * BST + lb_n] = v;
        }
        __syncthreads();

        // ---- 4 k8 steps of m16n8k8 ----
        #pragma unroll
        for (int k8 = 0; k8 < 4; k8++) {
            uint32_t a[2][4];
            #pragma unroll
            for (int mf = 0; mf < 2; mf++) {
                const float* ab = &As[(wm * 32 + mf * 16 + g) * AST + k8 * 8 + t];
                a[mf][0] = __float_as_uint(ab[0]);
                a[mf][1] = __float_as_uint(ab[8 * AST]);
                a[mf][2] = __float_as_uint(ab[4]);
                a[mf][3] = __float_as_uint(ab[8 * AST + 4]);
            }
            #pragma unroll
            for (int nf = 0; nf < 8; nf++) {
                const int n0 = wn * 64 + nf * 8;
                const uint32_t b0 = __float_as_uint(Bs[(k8 * 8 + t) * BST + n0 + g]);
                const uint32_t b1 = __float_as_uint(Bs[(k8 * 8 + t + 4) * BST + n0 + g]);
                mma_tf32(acc[0][nf], a[0], b0, b1);
                mma_tf32(acc[1][nf], a[1], b0, b1);
            }
        }
        __syncthreads();
    }

    // ---- epilogue: add bias, store fp32 ----
    #pragma unroll
    for (int mf = 0; mf < 2; mf++) {
        const size_t r0 = bm + wm * 32 + mf * 16 + g;
        #pragma unroll
        for (int nf = 0; nf < 8; nf++) {
            const int col = bn + wn * 64 + nf * 8 + 2 * t;
            const float bx = bias[col], by = bias[col + 1];
            *(float2*)&C[r0 * N + col] =
                make_float2(acc[mf][nf].x + bx, acc[mf][nf].y + by);
            *(float2*)&C[(r0 + 8) * N + col] =
                make_float2(acc[mf][nf].z + bx, acc[mf][nf].w + by);
        }
    }
}

// ---------------------------------------------------------------------------
// Causal flash attention, tf32 tensor-core (mma.sync) — unchanged from R7.
// ---------------------------------------------------------------------------
#define ST 72

__global__ __launch_bounds__(128)
void attn_mma(const float* __restrict__ qkv, float* __restrict__ attn) {
    __shared__ float KtPs[64 * ST];
    __shared__ float Vsm[64 * ST];

    const int tid  = threadIdx.x;
    const int lane = tid & 31;
    const int warp = tid >> 5;
    const int g    = lane >> 2;
    const int t    = lane & 3;
    const int h    = blockIdx.y;
    const int qt   = gridDim.x - 1 - blockIdx.x;   // heavy blocks first

    // ---- stage Q tile (rows [i][k], stride ST, tf32) ----
    {
        const int i  = tid >> 1;
        const int kb = (tid & 1) * 32;
        const float* qp = &qkv[(size_t)(qt * 64 + i) * QKVN + h * DH + kb];
        #pragma unroll
        for (int c = 0; c < 32; c += 4) {
            float4 v = *(const float4*)(qp + c);
            float4 w;
            w.x = f2tf32f(v.x); w.y = f2tf32f(v.y);
            w.z = f2tf32f(v.z); w.w = f2tf32f(v.w);
            *(float4*)&KtPs[i * ST + kb + c] = w;
        }
    }
    __syncthreads();

    uint32_t qf[8][4];
    #pragma unroll
    for (int k8 = 0; k8 < 8; k8++) {
        const float* qb = &KtPs[(warp * 16 + g) * ST + k8 * 8 + t];
        qf[k8][0] = __float_as_uint(qb[0]);
        qf[k8][1] = __float_as_uint(qb[8 * ST]);
        qf[k8][2] = __float_as_uint(qb[4]);
        qf[k8][3] = __float_as_uint(qb[8 * ST + 4]);
    }
    __syncthreads();

    float4 o[8];
    #pragma unroll
    for (int nt = 0; nt < 8; nt++) o[nt] = make_float4(0.f, 0.f, 0.f, 0.f);
    float m0 = -INFINITY, m1 = -INFINITY, l0 = 0.f, l1 = 0.f;

    const int row0 = warp * 16 + g;
    const int row1 = row0 + 8;

    for (int kt = 0; kt <= qt; kt++) {
        {
            const int j  = tid >> 1;
            const int kb = (tid & 1) * 32;
            const float* kp = &qkv[(size_t)(kt * 64 + j) * QKVN + DEMB + h * DH + kb];
            const float* vp = kp + DEMB;
            #pragma unroll
            for (int c = 0; c < 32; c += 4) {
                float4 kv = *(const float4*)(kp + c);
                KtPs[(kb + c + 0) * ST + j] = f2tf32f(kv.x);
                KtPs[(kb + c + 1) * ST + j] = f2tf32f(kv.y);
                KtPs[(kb + c + 2) * ST + j] = f2tf32f(kv.z);
                KtPs[(kb + c + 3) * ST + j] = f2tf32f(kv.w);
                float4 vv = *(const float4*)(vp + c);
                float4 w;
                w.x = f2tf32f(vv.x); w.y = f2tf32f(vv.y);
                w.z = f2tf32f(vv.z); w.w = f2tf32f(vv.w);
                *(float4*)&Vsm[j * ST + kb + c] = w;
            }
        }
        __syncthreads();

        float4 s[8];
        #pragma unroll
        for (int nt = 0; nt < 8; nt++) s[nt] = make_float4(0.f, 0.f, 0.f, 0.f);
        #pragma unroll
        for (int nt = 0; nt < 8; nt++) {
            #pragma unroll
            for (int k8 = 0; k8 < 8; k8++) {
                const uint32_t b0 = __float_as_uint(KtPs[(k8 * 8 + t) * ST + nt * 8 + g]);
                const uint32_t b1 = __float_as_uint(KtPs[(k8 * 8 + t + 4) * ST + nt * 8 + g]);
                mma_tf32(s[nt], qf[k8], b0, b1);
            }
        }
        __syncthreads();

        const bool diag = (kt == qt);
        #pragma unroll
        for (int nt = 0; nt < 8; nt++) {
            s[nt].x *= 0.125f; s[nt].y *= 0.125f;
            s[nt].z *= 0.125f; s[nt].w *= 0.125f;
            if (diag) {
                const int col = nt * 8 + 2 * t;
                if (col     > row0) s[nt].x = -INFINITY;
                if (col + 1 > row0) s[nt].y = -INFINITY;
                if (col     > row1) s[nt].z = -INFINITY;
                if (col + 1 > row1) s[nt].w = -INFINITY;
            }
        }

        float mx0 = -INFINITY, mx1 = -INFINITY;
        #pragma unroll
        for (int nt = 0; nt < 8; nt++) {
            mx0 = fmaxf(mx0, fmaxf(s[nt].x, s[nt].y));
            mx1 = fmaxf(mx1, fmaxf(s[nt].z, s[nt].w));
        }
        mx0 = fmaxf(mx0, __shfl_xor_sync(0xffffffffu, mx0, 1));
        mx0 = fmaxf(mx0, __shfl_xor_sync(0xffffffffu, mx0, 2));
        mx1 = fmaxf(mx1, __shfl_xor_sync(0xffffffffu, mx1, 1));
        mx1 = fmaxf(mx1, __shfl_xor_sync(0xffffffffu, mx1, 2));

        const float mn0 = fmaxf(m0, mx0);
        const float mn1 = fmaxf(m1, mx1);
        const float corr0 = __expf(m0 - mn0);
        const float corr1 = __expf(m1 - mn1);
        m0 = mn0; m1 = mn1;

        float sum0 = 0.f, sum1 = 0.f;
        #pragma unroll
        for (int nt = 0; nt < 8; nt++) {
            s[nt].x = __expf(s[nt].x - mn0);
            s[nt].y = __expf(s[nt].y - mn0);
            s[nt].z = __expf(s[nt].z - mn1);
            s[nt].w = __expf(s[nt].w - mn1);
            sum0 += s[nt].x + s[nt].y;
            sum1 += s[nt].z + s[nt].w;
        }
        sum0 += __shfl_xor_sync(0xffffffffu, sum0, 1);
        sum0 += __shfl_xor_sync(0xffffffffu, sum0, 2);
        sum1 += __shfl_xor_sync(0xffffffffu, sum1, 1);
        sum1 += __shfl_xor_sync(0xffffffffu, sum1, 2);
        l0 = l0 * corr0 + sum0;
        l1 = l1 * corr1 + sum1;
        #pragma unroll
        for (int nt = 0; nt < 8; nt++) {
            o[nt].x *= corr0; o[nt].y *= corr0;
            o[nt].z *= corr1; o[nt].w *= corr1;
        }

        #pragma unroll
        for (int nt = 0; nt < 8; nt++) {
            float2 p01 = make_float2(f2tf32f(s[nt].x), f2tf32f(s[nt].y));
            float2 p23 = make_float2(f2tf32f(s[nt].z), f2tf32f(s[nt].w));
            *(float2*)&KtPs[row0 * ST + nt * 8 + 2 * t] = p01;
            *(float2*)&KtPs[row1 * ST + nt * 8 + 2 * t] = p23;
        }
        __syncthreads();

        #pragma unroll
        for (int k8 = 0; k8 < 8; k8++) {
            uint32_t a[4];
            const float* pb = &KtPs[row0 * ST + k8 * 8 + t];
            a[0] = __float_as_uint(pb[0]);
            a[1] = __float_as_uint(pb[8 * ST]);
            a[2] = __float_as_uint(pb[4]);
            a[3] = __float_as_uint(pb[8 * ST + 4]);
            #pragma unroll
            for (int nt = 0; nt < 8; nt++) {
                const uint32_t b0 = __float_as_uint(Vsm[(k8 * 8 + t) * ST + nt * 8 + g]);
                const uint32_t b1 = __float_as_uint(Vsm[(k8 * 8 + t + 4) * ST + nt * 8 + g]);
                mma_tf32(o[nt], a, b0, b1);
            }
        }
        __syncthreads();
    }

    const float inv0 = 1.f / l0;
    const float inv1 = 1.f / l1;
    const size_t gr0 = (size_t)(qt * 64 + row0) * DEMB + h * DH;
    const size_t gr1 = (size_t)(qt * 64 + row1) * DEMB + h * DH;
    #pragma unroll
    for (int nt = 0; nt < 8; nt++) {
        const int col = nt * 8 + 2 * t;
        *(float2*)&attn[gr0 + col] = make_float2(o[nt].x * inv0, o[nt].y * inv0);
        *(float2*)&attn[gr1 + col] = make_float2(o[nt].z * inv1, o[nt].w * inv1);
    }
}

// ---------------------------------------------------------------------------
// Launch
// ---------------------------------------------------------------------------
extern "C" void kernel_launch(void* const* d_in, const int* in_sizes, int n_in,
                              void* d_out, int out_size) {
    const float* x     = (const float*)d_in[0];
    const float* W_in  = (const float*)d_in[1];
    const float* b_in  = (const float*)d_in[2];
    const float* W_out = (const float*)d_in[3];
    const float* b_out = (const float*)d_in[4];
    float* out = (float*)d_out;

    float* qkv  = nullptr;
    float* attn = nullptr;
    cudaGetSymbolAddress((void**)&qkv,  g_qkv);
    cudaGetSymbolAddress((void**)&attn, g_attn);

    gemm_bias<<<dim3(QKVN / 128, SEQ / 128), 256>>>(x, W_in, b_in, qkv,
                                                    SEQ, QKVN, DEMB);
    attn_mma<<<dim3(SEQ / 64, NH), 128>>>(qkv, attn);
    gemm_bias<<<dim3(DEMB / 128, SEQ / 128), 256>>>(attn, W_out, b_out, out,
                                                    SEQ, DEMB, DEMB);
}